// round 3
// baseline (speedup 1.0000x reference)
#include <cuda_runtime.h>
#include <cstdint>

// Problem constants (B=4, L=4096, D=64 — fixed by the dataset).
#define Bc 4
#define Lc 4096
#define Dc 64
#define TQ 128               // q rows per CTA
#define TK 128               // k rows per chunk
#define NCHUNK (Lc / TK)     // 32
#define NTHREADS 256
#define EPSf 1e-7f

// ---- packed fp32x2 FMA (Blackwell): doubles fp32 FMA throughput vs FFMA ----
union F2 { float2 f; unsigned long long u; };

__device__ __forceinline__ void ffma2(F2& d, const F2& a, const F2& b) {
    asm("fma.rn.f32x2 %0, %1, %2, %0;" : "+l"(d.u) : "l"(a.u), "l"(b.u));
}

// ---- register-resident descending top-5 (values are exp(logit) > 0) ----
struct Top5 {
    float v0, v1, v2, v3, v4;
    int   i0, i1, i2, i3, i4;
    __device__ __forceinline__ void init() {
        v0 = v1 = v2 = v3 = v4 = -1.0f;
        i0 = i1 = i2 = i3 = i4 = 0;
    }
    __device__ __forceinline__ void insert(float e, int idx) {
        if (e <= v4) return;
        if (e > v2) {
            if (e > v0) {
                v4=v3; i4=i3; v3=v2; i3=i2; v2=v1; i2=i1; v1=v0; i1=i0; v0=e; i0=idx;
            } else if (e > v1) {
                v4=v3; i4=i3; v3=v2; i3=i2; v2=v1; i2=i1; v1=e; i1=idx;
            } else {
                v4=v3; i4=i3; v3=v2; i3=i2; v2=e; i2=idx;
            }
        } else {
            if (e > v3) { v4=v3; i4=i3; v3=e; i3=idx; }
            else        { v4=e;  i4=idx; }
        }
    }
};

// Shared memory layout (floats):
//   Qt   [    0,  8192)  : Q tile transposed [64][128], pre-scaled by 1/8
//   Kt   [ 8192, 16384)  : K chunk transposed [64][128]
//   sZ   [16384, 18432)  : per-(row,txgroup) partial softmax denominators 128*16
//   sV   [18432, 28672)  : per-partial top5 values 128*16*5
//   sI   [28672, 38912)  : per-partial top5 indices 128*16*5 (int)
//   sW   [38912, 39552)  : per-row final weights 128*5
//   sIdx [39552, 40192)  : per-row final indices 128*5 (int)
#define SMEM_FLOATS 40192
#define SMEM_BYTES  (SMEM_FLOATS * 4)

extern "C" __global__ void __launch_bounds__(NTHREADS, 1)
sparse_attn_kernel(const float* __restrict__ q,
                   const float* __restrict__ k,
                   const float* __restrict__ v,
                   float* __restrict__ out,     // may be null (attn-only mode)
                   float* __restrict__ attn)    // may be null (out-only mode)
{
    extern __shared__ float smem[];
    float* Qt   = smem;
    float* Kt   = smem + 8192;
    float* sZ   = smem + 16384;
    float* sV   = smem + 18432;
    int*   sI   = (int*)(smem + 28672);
    float* sW   = smem + 38912;
    int*   sIdx = (int*)(smem + 39552);

    const int tid = threadIdx.x;
    const int ty  = tid >> 4;      // 0..15 : q sub-block
    const int tx  = tid & 15;      // 0..15 : k sub-block
    const int bq  = blockIdx.x;    // q tile index within batch
    const int b   = blockIdx.y;    // batch

    const float* qb = q + ((size_t)b * Lc + (size_t)bq * TQ) * Dc;
    const float* kb = k + (size_t)b * Lc * Dc;
    const float* vb = v + (size_t)b * Lc * Dc;

    // ---- load Q tile, transpose into Qt[d][row], apply 1/temperature ----
    for (int i = tid; i < TQ * (Dc / 4); i += NTHREADS) {
        int row = i >> 4, seg = i & 15;
        float4 t = *(const float4*)(qb + row * Dc + seg * 4);
        Qt[(seg * 4 + 0) * TQ + row] = t.x * 0.125f;
        Qt[(seg * 4 + 1) * TQ + row] = t.y * 0.125f;
        Qt[(seg * 4 + 2) * TQ + row] = t.z * 0.125f;
        Qt[(seg * 4 + 3) * TQ + row] = t.w * 0.125f;
    }

    // ---- zero-fill this CTA's attn rows (contiguous 128*4096 f32 block).
    // Fire-and-forget stores; drained by HBM while the compute loop runs. ----
    if (attn) {
        float4 z4 = make_float4(0.f, 0.f, 0.f, 0.f);
        float4* ap = (float4*)(attn + ((size_t)b * Lc + (size_t)bq * TQ) * Lc);
        const int n4 = TQ * Lc / 4;  // 131072
        for (int i = tid; i < n4; i += NTHREADS) ap[i] = z4;
    }

    float Zl[8];
    Top5 top[8];
    #pragma unroll
    for (int i = 0; i < 8; i++) { Zl[i] = 0.f; top[i].init(); }

    for (int ch = 0; ch < NCHUNK; ch++) {
        __syncthreads();  // protect Kt from previous iteration's readers
        // ---- load K chunk, transpose into Kt[d][col] ----
        for (int i = tid; i < TK * (Dc / 4); i += NTHREADS) {
            int row = i >> 4, seg = i & 15;
            float4 t = *(const float4*)(kb + (ch * TK + row) * Dc + seg * 4);
            Kt[(seg * 4 + 0) * TK + row] = t.x;
            Kt[(seg * 4 + 1) * TK + row] = t.y;
            Kt[(seg * 4 + 2) * TK + row] = t.z;
            Kt[(seg * 4 + 3) * TK + row] = t.w;
        }
        __syncthreads();

        // ---- 128x128 S tile: 8x8 per thread, rows packed in f32x2 pairs ----
        F2 acc[4][8];
        #pragma unroll
        for (int p = 0; p < 4; p++)
            #pragma unroll
            for (int j = 0; j < 8; j++) acc[p][j].f = make_float2(0.f, 0.f);

        #pragma unroll 8
        for (int kk = 0; kk < Dc; kk++) {
            float4 a0 = *(const float4*)(Qt + kk * TQ + ty * 8);
            float4 a1 = *(const float4*)(Qt + kk * TQ + ty * 8 + 4);
            float4 b0 = *(const float4*)(Kt + kk * TK + tx * 8);
            float4 b1 = *(const float4*)(Kt + kk * TK + tx * 8 + 4);
            F2 ap[4];
            ap[0].f = make_float2(a0.x, a0.y);
            ap[1].f = make_float2(a0.z, a0.w);
            ap[2].f = make_float2(a1.x, a1.y);
            ap[3].f = make_float2(a1.z, a1.w);
            float bs[8] = {b0.x, b0.y, b0.z, b0.w, b1.x, b1.y, b1.z, b1.w};
            #pragma unroll
            for (int j = 0; j < 8; j++) {
                F2 bd; bd.f = make_float2(bs[j], bs[j]);
                ffma2(acc[0][j], ap[0], bd);
                ffma2(acc[1][j], ap[1], bd);
                ffma2(acc[2][j], ap[2], bd);
                ffma2(acc[3][j], ap[3], bd);
            }
        }

        // ---- per-chunk epilogue: softmax partial sums + top-5 tracking ----
        const int cbase = ch * TK + tx * 8;
        #pragma unroll
        for (int p = 0; p < 4; p++) {
            #pragma unroll
            for (int j = 0; j < 8; j++) {
                float e0 = __expf(acc[p][j].f.x);
                float e1 = __expf(acc[p][j].f.y);
                Zl[2 * p]     += e0;
                Zl[2 * p + 1] += e1;
                top[2 * p].insert(e0, cbase + j);
                top[2 * p + 1].insert(e1, cbase + j);
            }
        }
    }

    __syncthreads();
    // ---- dump per-thread partials (16 partials per q-row) ----
    #pragma unroll
    for (int i = 0; i < 8; i++) {
        int row  = ty * 8 + i;
        int base = row * 16 + tx;
        sZ[base] = Zl[i];
        sV[base * 5 + 0] = top[i].v0; sI[base * 5 + 0] = top[i].i0;
        sV[base * 5 + 1] = top[i].v1; sI[base * 5 + 1] = top[i].i1;
        sV[base * 5 + 2] = top[i].v2; sI[base * 5 + 2] = top[i].i2;
        sV[base * 5 + 3] = top[i].v3; sI[base * 5 + 3] = top[i].i3;
        sV[base * 5 + 4] = top[i].v4; sI[base * 5 + 4] = top[i].i4;
    }
    __syncthreads();

    // ---- one thread per q-row: merge, sparsify, scatter attn nonzeros ----
    if (tid < TQ) {
        int row = tid;
        float Z = 0.f;
        Top5 m; m.init();
        for (int x = 0; x < 16; x++) {
            int base = row * 16 + x;
            Z += sZ[base];
            m.insert(sV[base * 5 + 0], sI[base * 5 + 0]);
            m.insert(sV[base * 5 + 1], sI[base * 5 + 1]);
            m.insert(sV[base * 5 + 2], sI[base * 5 + 2]);
            m.insert(sV[base * 5 + 3], sI[base * 5 + 3]);
            m.insert(sV[base * 5 + 4], sI[base * 5 + 4]);
        }
        // p_i = e_i / Z ; delta = p_(5) + eps ; w = max(p - delta, 0) / (sum(w)+eps)
        float delta = m.v4 / Z + EPSf;
        float w0 = fmaxf(m.v0 / Z - delta, 0.f);
        float w1 = fmaxf(m.v1 / Z - delta, 0.f);
        float w2 = fmaxf(m.v2 / Z - delta, 0.f);
        float w3 = fmaxf(m.v3 / Z - delta, 0.f);
        float w4 = fmaxf(m.v4 / Z - delta, 0.f);  // always 0, kept for fidelity
        float denom = w0 + w1 + w2 + w3 + w4 + EPSf;
        w0 /= denom; w1 /= denom; w2 /= denom; w3 /= denom; w4 /= denom;

        sW[row * 5 + 0] = w0; sIdx[row * 5 + 0] = m.i0;
        sW[row * 5 + 1] = w1; sIdx[row * 5 + 1] = m.i1;
        sW[row * 5 + 2] = w2; sIdx[row * 5 + 2] = m.i2;
        sW[row * 5 + 3] = w3; sIdx[row * 5 + 3] = m.i3;
        sW[row * 5 + 4] = w4; sIdx[row * 5 + 4] = m.i4;

        if (attn) {
            float* arow = attn + ((size_t)b * Lc + (size_t)bq * TQ + row) * Lc;
            arow[m.i0] = w0;
            arow[m.i1] = w1;
            arow[m.i2] = w2;
            arow[m.i3] = w3;
            arow[m.i4] = w4;   // writes 0 over the zero background — harmless
        }
    }
    __syncthreads();

    // ---- out = sparse attn @ v : gather 5 v-rows per q-row.
    // 2 threads per row, 32 dims each. ----
    if (out) {
        int row  = tid >> 1;
        int half = tid & 1;
        float4 o[8];
        #pragma unroll
        for (int s = 0; s < 8; s++) o[s] = make_float4(0.f, 0.f, 0.f, 0.f);
        #pragma unroll
        for (int t = 0; t < 5; t++) {
            float wt = sW[row * 5 + t];
            const float4* vr =
                (const float4*)(vb + (size_t)sIdx[row * 5 + t] * Dc + half * 32);
            #pragma unroll
            for (int s = 0; s < 8; s++) {
                float4 x = vr[s];
                o[s].x += wt * x.x; o[s].y += wt * x.y;
                o[s].z += wt * x.z; o[s].w += wt * x.w;
            }
        }
        float4* orow =
            (float4*)(out + ((size_t)b * Lc + (size_t)bq * TQ + row) * Dc + half * 32);
        #pragma unroll
        for (int s = 0; s < 8; s++) orow[s] = o[s];
    }
}

extern "C" void kernel_launch(void* const* d_in, const int* in_sizes, int n_in,
                              void* d_out, int out_size) {
    const float* q = (const float*)d_in[0];
    const float* k = (const float*)d_in[1];
    const float* v = (const float*)d_in[2];

    const size_t outElems  = (size_t)Bc * Lc * Dc;              //  1,048,576
    const size_t attnElems = (size_t)Bc * Lc * (size_t)Lc;      // 67,108,864

    // Decide layout from the actual buffer size — never write past d_out.
    float* out  = nullptr;
    float* attn = nullptr;
    size_t total = (size_t)out_size;
    if (total >= outElems + attnElems) {
        // (out, attn) concatenated: out first, then attn.
        out  = (float*)d_out;
        attn = (float*)d_out + outElems;
    } else if (total >= attnElems) {
        // attn only fits: treat the whole buffer as attn.
        attn = (float*)d_out;
    } else {
        // only out fits.
        out = (float*)d_out;
    }

    cudaFuncSetAttribute(sparse_attn_kernel,
                         cudaFuncAttributeMaxDynamicSharedMemorySize, SMEM_BYTES);

    dim3 grid(Lc / TQ, Bc);   // (32, 4) = 128 CTAs
    sparse_attn_kernel<<<grid, NTHREADS, SMEM_BYTES>>>(q, k, v, out, attn);
}

// round 4
// speedup vs baseline: 1.1226x; 1.1226x over previous
#include <cuda_runtime.h>
#include <cstdint>

// Problem constants (B=4, L=4096, D=64 — fixed by the dataset).
#define Bc 4
#define Lc 4096
#define Dc 64
#define TQ 64                // q rows per CTA
#define TK 256               // k rows per chunk
#define NCHUNK (Lc / TK)     // 16
#define NTHREADS 256
#define EPSf 1e-7f

// ---- packed fp32x2 FMA (Blackwell): doubles fp32 FMA throughput ----
union F2 { float2 f; unsigned long long u; };
__device__ __forceinline__ void ffma2(F2& d, const F2& a, const F2& b) {
    asm("fma.rn.f32x2 %0, %1, %2, %0;" : "+l"(d.u) : "l"(a.u), "l"(b.u));
}

// ---- 32-bit sortable key: [monotone float bits, 11-bit mantissa][12-bit col idx]
__device__ __forceinline__ unsigned key_pack(float s, int col) {
    unsigned u = __float_as_uint(s);
    u ^= (unsigned)((int)u >> 31) | 0x80000000u;   // sign-flip trick: order-preserving
    return (u & 0xFFFFF000u) | (unsigned)col;       // truncate 12 LSBs, embed col
}

// Shared memory layout (floats):
//   Qt   [    0,  4096)  : Q tile transposed [64 d][64 row], pre-scaled 1/8
//   Kt   [ 4096, 20480)  : K chunk transposed [64 d][256 col]
//        (after mainloop, Kt space is reused as scratch:
//           keys : uint [64 row][32 tx][5]  = 10240 @ Kt+0
//           sZs  : float[64 row][32 tx]     =  2048 @ Kt+10240)
//   sW   [20480, 20800)  : final weights 64*5
//   sIdx [20800, 21120)  : final indices 64*5 (int)
#define SMEM_FLOATS 21120
#define SMEM_BYTES  (SMEM_FLOATS * 4)

extern "C" __global__ void __launch_bounds__(NTHREADS, 2)
sparse_attn_kernel(const float* __restrict__ q,
                   const float* __restrict__ k,
                   const float* __restrict__ v,
                   float* __restrict__ out,     // may be null
                   float* __restrict__ attn)    // may be null
{
    extern __shared__ float smem[];
    float* Qt   = smem;                 // [d*64 + row]
    float* Kt   = smem + 4096;          // [d*256 + col]
    float* sW   = smem + 20480;
    int*   sIdx = (int*)(smem + 20800);
    unsigned* sK  = (unsigned*)(smem + 4096);          // scratch alias (post-loop)
    float*    sZs = smem + 4096 + 10240;               // scratch alias (post-loop)

    const int tid = threadIdx.x;
    const int ty  = tid >> 5;      // 0..7  : q sub-block (8 rows each)
    const int tx  = tid & 31;      // 0..31 : k sub-block (8 cols each)
    const int bq  = blockIdx.x;    // q tile (64 rows)
    const int b   = blockIdx.y;    // batch

    const float* qb = q + ((size_t)b * Lc + (size_t)bq * TQ) * Dc;
    const float* kb = k + (size_t)b * Lc * Dc;
    const float* vb = v + (size_t)b * Lc * Dc;

    // ---- Q tile -> Qt[d][row], scaled by 1/temperature. Warp = 32 rows,
    // fixed seg -> STS banks = row%32 : conflict-free. ----
    #pragma unroll
    for (int it = 0; it < 4; it++) {
        int idx = it * NTHREADS + tid;      // 0..1023
        int row = idx & 63, seg = idx >> 6; // seg 0..15
        float4 t = *(const float4*)(qb + row * Dc + seg * 4);
        Qt[(seg * 4 + 0) * TQ + row] = t.x * 0.125f;
        Qt[(seg * 4 + 1) * TQ + row] = t.y * 0.125f;
        Qt[(seg * 4 + 2) * TQ + row] = t.z * 0.125f;
        Qt[(seg * 4 + 3) * TQ + row] = t.w * 0.125f;
    }

    // ---- zero-fill this CTA's attn rows (64*4096 f32, contiguous) ----
    if (attn) {
        float4 z4 = make_float4(0.f, 0.f, 0.f, 0.f);
        float4* ap = (float4*)(attn + ((size_t)b * Lc + (size_t)bq * TQ) * Lc);
        #pragma unroll 4
        for (int i = tid; i < TQ * Lc / 4; i += NTHREADS) ap[i] = z4;
    }

    float    Zl[8];
    unsigned key[8][5];                    // descending per row
    #pragma unroll
    for (int r = 0; r < 8; r++) {
        Zl[r] = 0.f;
        #pragma unroll
        for (int t = 0; t < 5; t++) key[r][t] = 0u;
    }

    for (int ch = 0; ch < NCHUNK; ch++) {
        __syncthreads();  // protect Kt from previous readers
        // ---- K chunk -> Kt[d][col]. Warp = 32 cols, fixed seg: STS conflict-free.
        #pragma unroll
        for (int it = 0; it < 16; it++) {
            int idx = it * NTHREADS + tid;        // 0..4095
            int col = idx & 255, seg = idx >> 8;  // seg 0..15
            float4 t = *(const float4*)(kb + ((size_t)ch * TK + col) * Dc + seg * 4);
            Kt[(seg * 4 + 0) * TK + col] = t.x;
            Kt[(seg * 4 + 1) * TK + col] = t.y;
            Kt[(seg * 4 + 2) * TK + col] = t.z;
            Kt[(seg * 4 + 3) * TK + col] = t.w;
        }
        __syncthreads();

        // ---- 64x256 S tile: 8x8 per thread, rows packed in f32x2 pairs ----
        F2 acc[4][8];
        #pragma unroll
        for (int p = 0; p < 4; p++)
            #pragma unroll
            for (int j = 0; j < 8; j++) acc[p][j].f = make_float2(0.f, 0.f);

        #pragma unroll 8
        for (int kk = 0; kk < Dc; kk++) {
            float4 a0 = *(const float4*)(Qt + kk * TQ + ty * 8);       // bcast
            float4 a1 = *(const float4*)(Qt + kk * TQ + ty * 8 + 4);   // bcast
            float4 b0 = *(const float4*)(Kt + kk * TK + tx * 8);
            float4 b1 = *(const float4*)(Kt + kk * TK + tx * 8 + 4);
            F2 ap0, ap1, ap2, ap3;
            ap0.f = make_float2(a0.x, a0.y);
            ap1.f = make_float2(a0.z, a0.w);
            ap2.f = make_float2(a1.x, a1.y);
            ap3.f = make_float2(a1.z, a1.w);
            float bs[8] = {b0.x, b0.y, b0.z, b0.w, b1.x, b1.y, b1.z, b1.w};
            #pragma unroll
            for (int j = 0; j < 8; j++) {
                F2 bd; bd.f = make_float2(bs[j], bs[j]);
                ffma2(acc[0][j], ap0, bd);
                ffma2(acc[1][j], ap1, bd);
                ffma2(acc[2][j], ap2, bd);
                ffma2(acc[3][j], ap3, bd);
            }
        }

        // ---- epilogue: Z partial sums + packed-key top-5 ----
        const int cbase = ch * TK + tx * 8;
        #pragma unroll
        for (int p = 0; p < 4; p++) {
            #pragma unroll
            for (int j = 0; j < 8; j++) {
                float s0 = acc[p][j].f.x;
                float s1 = acc[p][j].f.y;
                Zl[2 * p]     += __expf(s0);
                Zl[2 * p + 1] += __expf(s1);
                unsigned k0 = key_pack(s0, cbase + j);
                unsigned k1 = key_pack(s1, cbase + j);
                // row 2p
                {
                    unsigned* K5 = key[2 * p];
                    if (k0 > K5[4]) {
                        if (k0 > K5[2]) {
                            if (k0 > K5[0])      { K5[4]=K5[3];K5[3]=K5[2];K5[2]=K5[1];K5[1]=K5[0];K5[0]=k0; }
                            else if (k0 > K5[1]) { K5[4]=K5[3];K5[3]=K5[2];K5[2]=K5[1];K5[1]=k0; }
                            else                 { K5[4]=K5[3];K5[3]=K5[2];K5[2]=k0; }
                        } else {
                            if (k0 > K5[3]) { K5[4]=K5[3]; K5[3]=k0; } else K5[4]=k0;
                        }
                    }
                }
                // row 2p+1
                {
                    unsigned* K5 = key[2 * p + 1];
                    if (k1 > K5[4]) {
                        if (k1 > K5[2]) {
                            if (k1 > K5[0])      { K5[4]=K5[3];K5[3]=K5[2];K5[2]=K5[1];K5[1]=K5[0];K5[0]=k1; }
                            else if (k1 > K5[1]) { K5[4]=K5[3];K5[3]=K5[2];K5[2]=K5[1];K5[1]=k1; }
                            else                 { K5[4]=K5[3];K5[3]=K5[2];K5[2]=k1; }
                        } else {
                            if (k1 > K5[3]) { K5[4]=K5[3]; K5[3]=k1; } else K5[4]=k1;
                        }
                    }
                }
            }
        }
    }

    __syncthreads();   // all Kt reads done; safe to alias scratch over Kt
    // ---- dump partials: 32 partials per row ----
    #pragma unroll
    for (int r = 0; r < 8; r++) {
        int row = ty * 8 + r;
        sZs[row * 32 + tx] = Zl[r];
        unsigned* dst = sK + (row * 32 + tx) * 5;
        #pragma unroll
        for (int t = 0; t < 5; t++) dst[t] = key[r][t];
    }
    __syncthreads();

    // ---- one thread per q-row: merge keys, recompute logits, sparsify ----
    if (tid < TQ) {
        const int row = tid;
        float Z = 0.f;
        unsigned m0 = 0, m1 = 0, m2 = 0, m3 = 0, m4 = 0;
        for (int x = 0; x < 32; x++) {
            Z += sZs[row * 32 + x];
            const unsigned* src = sK + (row * 32 + x) * 5;
            #pragma unroll
            for (int t = 0; t < 5; t++) {
                unsigned kk = src[t];
                if (kk <= m4) break;       // lists are sorted descending
                if (kk > m2) {
                    if (kk > m0)      { m4=m3; m3=m2; m2=m1; m1=m0; m0=kk; }
                    else if (kk > m1) { m4=m3; m3=m2; m2=m1; m1=kk; }
                    else              { m4=m3; m3=m2; m2=kk; }
                } else {
                    if (kk > m3) { m4=m3; m3=kk; } else m4=kk;
                }
            }
        }
        int idx5[5] = { (int)(m0 & 0xFFFu), (int)(m1 & 0xFFFu), (int)(m2 & 0xFFFu),
                        (int)(m3 & 0xFFFu), (int)(m4 & 0xFFFu) };
        // exact logits for the 5 winners: Qt (pre-scaled) . k[idx]
        float e5[5];
        #pragma unroll
        for (int t = 0; t < 5; t++) {
            const float4* kr = (const float4*)(kb + (size_t)idx5[t] * Dc);
            float s = 0.f;
            #pragma unroll
            for (int d4 = 0; d4 < 16; d4++) {
                float4 kv = kr[d4];
                s += Qt[(d4 * 4 + 0) * TQ + row] * kv.x;
                s += Qt[(d4 * 4 + 1) * TQ + row] * kv.y;
                s += Qt[(d4 * 4 + 2) * TQ + row] * kv.z;
                s += Qt[(d4 * 4 + 3) * TQ + row] * kv.w;
            }
            e5[t] = __expf(s);
        }
        float invZ = 1.0f / Z;
        float pmin = fminf(fminf(fminf(e5[0], e5[1]), fminf(e5[2], e5[3])), e5[4]);
        float delta = pmin * invZ + EPSf;
        float w[5], wsum = 0.f;
        #pragma unroll
        for (int t = 0; t < 5; t++) { w[t] = fmaxf(e5[t] * invZ - delta, 0.f); wsum += w[t]; }
        float inv = 1.0f / (wsum + EPSf);
        #pragma unroll
        for (int t = 0; t < 5; t++) {
            w[t] *= inv;
            sW[row * 5 + t]   = w[t];
            sIdx[row * 5 + t] = idx5[t];
        }
        if (attn) {
            float* arow = attn + ((size_t)b * Lc + (size_t)bq * TQ + row) * Lc;
            #pragma unroll
            for (int t = 0; t < 5; t++) arow[idx5[t]] = w[t];
        }
    }
    __syncthreads();

    // ---- out = sparse attn @ v : 4 threads per row, 16 dims each ----
    if (out) {
        int row  = tid >> 2;       // 0..63
        int part = tid & 3;        // 16 floats = 4 float4
        float4 o[4];
        #pragma unroll
        for (int s = 0; s < 4; s++) o[s] = make_float4(0.f, 0.f, 0.f, 0.f);
        #pragma unroll
        for (int t = 0; t < 5; t++) {
            float wt = sW[row * 5 + t];
            const float4* vr =
                (const float4*)(vb + (size_t)sIdx[row * 5 + t] * Dc + part * 16);
            #pragma unroll
            for (int s = 0; s < 4; s++) {
                float4 x = vr[s];
                o[s].x += wt * x.x; o[s].y += wt * x.y;
                o[s].z += wt * x.z; o[s].w += wt * x.w;
            }
        }
        float4* orow =
            (float4*)(out + ((size_t)b * Lc + (size_t)bq * TQ + row) * Dc + part * 16);
        #pragma unroll
        for (int s = 0; s < 4; s++) orow[s] = o[s];
    }
}

extern "C" void kernel_launch(void* const* d_in, const int* in_sizes, int n_in,
                              void* d_out, int out_size) {
    const float* q = (const float*)d_in[0];
    const float* k = (const float*)d_in[1];
    const float* v = (const float*)d_in[2];

    const size_t outElems  = (size_t)Bc * Lc * Dc;          //  1,048,576
    const size_t attnElems = (size_t)Bc * Lc * (size_t)Lc;  // 67,108,864

    float* out  = nullptr;
    float* attn = nullptr;
    size_t total = (size_t)out_size;
    if (total >= outElems + attnElems) {
        out  = (float*)d_out;
        attn = (float*)d_out + outElems;
    } else if (total >= attnElems) {
        attn = (float*)d_out;
    } else {
        out = (float*)d_out;
    }

    cudaFuncSetAttribute(sparse_attn_kernel,
                         cudaFuncAttributeMaxDynamicSharedMemorySize, SMEM_BYTES);

    dim3 grid(Lc / TQ, Bc);   // (64, 4) = 256 CTAs -> 2 per SM
    sparse_attn_kernel<<<grid, NTHREADS, SMEM_BYTES>>>(q, k, v, out, attn);
}

// round 5
// speedup vs baseline: 1.1416x; 1.0169x over previous
#include <cuda_runtime.h>
#include <cstdint>

// Problem constants (B=4, L=4096, D=64 — fixed by the dataset).
#define Bc 4
#define Lc 4096
#define Dc 64
#define TQ 64                // q rows per CTA
#define TK 256               // k rows per chunk
#define NCHUNK (Lc / TK)     // 16
#define NTHREADS 256
#define EPSf 1e-7f

// ---- packed fp32x2 FMA (Blackwell): doubles fp32 FMA throughput ----
union F2 { float2 f; unsigned long long u; };
__device__ __forceinline__ void ffma2(F2& d, const F2& a, const F2& b) {
    asm("fma.rn.f32x2 %0, %1, %2, %0;" : "+l"(d.u) : "l"(a.u), "l"(b.u));
}

// ---- 32-bit sortable key: [monotone float bits, 11-bit mantissa][12-bit col idx]
__device__ __forceinline__ unsigned key_pack(float s, int col) {
    unsigned u = __float_as_uint(s);
    u ^= (unsigned)((int)u >> 31) | 0x80000000u;   // order-preserving bit trick
    return (u & 0xFFFFF000u) | (unsigned)col;      // truncate 12 LSBs, embed col
}

__device__ __forceinline__ void ins5(unsigned* K5, unsigned kk) {
    if (kk > K5[4]) {
        if (kk > K5[2]) {
            if (kk > K5[0])      { K5[4]=K5[3];K5[3]=K5[2];K5[2]=K5[1];K5[1]=K5[0];K5[0]=kk; }
            else if (kk > K5[1]) { K5[4]=K5[3];K5[3]=K5[2];K5[2]=K5[1];K5[1]=kk; }
            else                 { K5[4]=K5[3];K5[3]=K5[2];K5[2]=kk; }
        } else {
            if (kk > K5[3]) { K5[4]=K5[3]; K5[3]=kk; } else K5[4]=kk;
        }
    }
}

// Shared memory layout (floats):
//   Qt   [    0,  4096)  : Q tile transposed [64 d][64 row], pre-scaled 1/8
//   Kt   [ 4096, 20480)  : K chunk transposed [64 d][256 col]
//        (after mainloop, aliased as scratch: keys uint[64][32][5] @ +0,
//                                             sZs  float[64][32]  @ +10240)
//   sW   [20480, 20800)  : final weights 64*5
//   sIdx [20800, 21120)  : final indices 64*5 (int)
#define SMEM_FLOATS 21120
#define SMEM_BYTES  (SMEM_FLOATS * 4)

extern "C" __global__ void __launch_bounds__(NTHREADS, 2)
sparse_attn_kernel(const float* __restrict__ q,
                   const float* __restrict__ k,
                   const float* __restrict__ v,
                   float* __restrict__ out,     // may be null
                   float* __restrict__ attn)    // may be null
{
    extern __shared__ float smem[];
    float* Qt   = smem;                 // [d*64 + row]
    float* Kt   = smem + 4096;          // [d*256 + col]
    float* sW   = smem + 20480;
    int*   sIdx = (int*)(smem + 20800);
    unsigned* sK  = (unsigned*)(smem + 4096);   // scratch alias (post-loop)
    float*    sZs = smem + 4096 + 10240;        // scratch alias (post-loop)

    const int tid = threadIdx.x;
    const int ty  = tid >> 5;      // 0..7  : q sub-block (8 rows each)
    const int tx  = tid & 31;      // 0..31 : k sub-block (two 4-col groups)
    const int bq  = blockIdx.x;    // q tile (64 rows)
    const int b   = blockIdx.y;    // batch

    const float* qb = q + ((size_t)b * Lc + (size_t)bq * TQ) * Dc;
    const float* kb = k + (size_t)b * Lc * Dc;
    const float* vb = v + (size_t)b * Lc * Dc;

    // ---- Q tile -> Qt[d][row], scaled by 1/temperature. ----
    #pragma unroll
    for (int it = 0; it < 4; it++) {
        int idx = it * NTHREADS + tid;      // 0..1023
        int row = idx & 63, seg = idx >> 6; // seg 0..15
        float4 t = *(const float4*)(qb + row * Dc + seg * 4);
        Qt[(seg * 4 + 0) * TQ + row] = t.x * 0.125f;
        Qt[(seg * 4 + 1) * TQ + row] = t.y * 0.125f;
        Qt[(seg * 4 + 2) * TQ + row] = t.z * 0.125f;
        Qt[(seg * 4 + 3) * TQ + row] = t.w * 0.125f;
    }

    // ---- zero-fill this CTA's attn rows (64*4096 f32, contiguous) ----
    if (attn) {
        float4 z4 = make_float4(0.f, 0.f, 0.f, 0.f);
        float4* ap = (float4*)(attn + ((size_t)b * Lc + (size_t)bq * TQ) * Lc);
        #pragma unroll 4
        for (int i = tid; i < TQ * Lc / 4; i += NTHREADS) ap[i] = z4;
    }

    float    Zl[8];
    unsigned key[8][5];                    // descending per row
    #pragma unroll
    for (int r = 0; r < 8; r++) {
        Zl[r] = 0.f;
        #pragma unroll
        for (int t = 0; t < 5; t++) key[r][t] = 0u;
    }

    for (int ch = 0; ch < NCHUNK; ch++) {
        __syncthreads();  // protect Kt from previous readers
        // ---- K chunk -> Kt[d][col] (warp = 32 cols, fixed seg: conflict-free)
        #pragma unroll
        for (int it = 0; it < 16; it++) {
            int idx = it * NTHREADS + tid;        // 0..4095
            int col = idx & 255, seg = idx >> 8;  // seg 0..15
            float4 t = *(const float4*)(kb + ((size_t)ch * TK + col) * Dc + seg * 4);
            Kt[(seg * 4 + 0) * TK + col] = t.x;
            Kt[(seg * 4 + 1) * TK + col] = t.y;
            Kt[(seg * 4 + 2) * TK + col] = t.z;
            Kt[(seg * 4 + 3) * TK + col] = t.w;
        }
        __syncthreads();

        // ---- 64x256 S tile: 8 rows x (4+4 cols) per thread.
        //      Col groups: G0 = tx*4..tx*4+3, G1 = 128+tx*4..+3.
        //      Lane b-addresses are 16B-contiguous -> 4 smem wavefronts. ----
        F2 acc[4][8];
        #pragma unroll
        for (int p = 0; p < 4; p++)
            #pragma unroll
            for (int j = 0; j < 8; j++) acc[p][j].f = make_float2(0.f, 0.f);

        #pragma unroll 8
        for (int kk = 0; kk < Dc; kk++) {
            float4 a0 = *(const float4*)(Qt + kk * TQ + ty * 8);       // bcast
            float4 a1 = *(const float4*)(Qt + kk * TQ + ty * 8 + 4);   // bcast
            float4 b0 = *(const float4*)(Kt + kk * TK + tx * 4);         // G0
            float4 b1 = *(const float4*)(Kt + kk * TK + 128 + tx * 4);   // G1
            F2 ap0, ap1, ap2, ap3;
            ap0.f = make_float2(a0.x, a0.y);
            ap1.f = make_float2(a0.z, a0.w);
            ap2.f = make_float2(a1.x, a1.y);
            ap3.f = make_float2(a1.z, a1.w);
            float bs[8] = {b0.x, b0.y, b0.z, b0.w, b1.x, b1.y, b1.z, b1.w};
            #pragma unroll
            for (int j = 0; j < 8; j++) {
                F2 bd; bd.f = make_float2(bs[j], bs[j]);
                ffma2(acc[0][j], ap0, bd);
                ffma2(acc[1][j], ap1, bd);
                ffma2(acc[2][j], ap2, bd);
                ffma2(acc[3][j], ap3, bd);
            }
        }

        // ---- epilogue: Z partial sums + packed-key top-5 ----
        const int cb0 = ch * TK + tx * 4;        // group 0 base col
        const int cb1 = ch * TK + 128 + tx * 4;  // group 1 base col
        #pragma unroll
        for (int p = 0; p < 4; p++) {
            #pragma unroll
            for (int j = 0; j < 8; j++) {
                int col = (j < 4) ? (cb0 + j) : (cb1 + (j - 4));
                float s0 = acc[p][j].f.x;
                float s1 = acc[p][j].f.y;
                Zl[2 * p]     += __expf(s0);
                Zl[2 * p + 1] += __expf(s1);
                ins5(key[2 * p],     key_pack(s0, col));
                ins5(key[2 * p + 1], key_pack(s1, col));
            }
        }
    }

    __syncthreads();   // all Kt reads done; safe to alias scratch over Kt
    // ---- dump partials: 32 partials per row ----
    #pragma unroll
    for (int r = 0; r < 8; r++) {
        int row = ty * 8 + r;
        sZs[row * 32 + tx] = Zl[r];
        unsigned* dst = sK + (row * 32 + tx) * 5;
        #pragma unroll
        for (int t = 0; t < 5; t++) dst[t] = key[r][t];
    }
    __syncthreads();

    // ---- one thread per q-row: merge keys, recompute logits, sparsify ----
    if (tid < TQ) {
        const int row = tid;
        float Z = 0.f;
        unsigned m0 = 0, m1 = 0, m2 = 0, m3 = 0, m4 = 0;
        for (int x = 0; x < 32; x++) {
            Z += sZs[row * 32 + x];
            const unsigned* src = sK + (row * 32 + x) * 5;
            #pragma unroll
            for (int t = 0; t < 5; t++) {
                unsigned kk = src[t];
                if (kk <= m4) break;       // lists sorted descending
                if (kk > m2) {
                    if (kk > m0)      { m4=m3; m3=m2; m2=m1; m1=m0; m0=kk; }
                    else if (kk > m1) { m4=m3; m3=m2; m2=m1; m1=kk; }
                    else              { m4=m3; m3=m2; m2=kk; }
                } else {
                    if (kk > m3) { m4=m3; m3=kk; } else m4=kk;
                }
            }
        }
        int idx5[5] = { (int)(m0 & 0xFFFu), (int)(m1 & 0xFFFu), (int)(m2 & 0xFFFu),
                        (int)(m3 & 0xFFFu), (int)(m4 & 0xFFFu) };
        // exact logits for the 5 winners: Qt (pre-scaled) . k[idx]
        float e5[5];
        #pragma unroll
        for (int t = 0; t < 5; t++) {
            const float4* kr = (const float4*)(kb + (size_t)idx5[t] * Dc);
            float s = 0.f;
            #pragma unroll
            for (int d4 = 0; d4 < 16; d4++) {
                float4 kv = kr[d4];
                s += Qt[(d4 * 4 + 0) * TQ + row] * kv.x;
                s += Qt[(d4 * 4 + 1) * TQ + row] * kv.y;
                s += Qt[(d4 * 4 + 2) * TQ + row] * kv.z;
                s += Qt[(d4 * 4 + 3) * TQ + row] * kv.w;
            }
            e5[t] = __expf(s);
        }
        float invZ = 1.0f / Z;
        float pmin = fminf(fminf(fminf(e5[0], e5[1]), fminf(e5[2], e5[3])), e5[4]);
        float delta = pmin * invZ + EPSf;
        float w[5], wsum = 0.f;
        #pragma unroll
        for (int t = 0; t < 5; t++) { w[t] = fmaxf(e5[t] * invZ - delta, 0.f); wsum += w[t]; }
        float inv = 1.0f / (wsum + EPSf);
        #pragma unroll
        for (int t = 0; t < 5; t++) {
            w[t] *= inv;
            sW[row * 5 + t]   = w[t];
            sIdx[row * 5 + t] = idx5[t];
        }
        if (attn) {
            float* arow = attn + ((size_t)b * Lc + (size_t)bq * TQ + row) * Lc;
            #pragma unroll
            for (int t = 0; t < 5; t++) arow[idx5[t]] = w[t];
        }
    }
    __syncthreads();

    // ---- out = sparse attn @ v : 4 threads per row, 16 dims each ----
    if (out) {
        int row  = tid >> 2;       // 0..63
        int part = tid & 3;        // 16 floats = 4 float4
        float4 o[4];
        #pragma unroll
        for (int s = 0; s < 4; s++) o[s] = make_float4(0.f, 0.f, 0.f, 0.f);
        #pragma unroll
        for (int t = 0; t < 5; t++) {
            float wt = sW[row * 5 + t];
            const float4* vr =
                (const float4*)(vb + (size_t)sIdx[row * 5 + t] * Dc + part * 16);
            #pragma unroll
            for (int s = 0; s < 4; s++) {
                float4 x = vr[s];
                o[s].x += wt * x.x; o[s].y += wt * x.y;
                o[s].z += wt * x.z; o[s].w += wt * x.w;
            }
        }
        float4* orow =
            (float4*)(out + ((size_t)b * Lc + (size_t)bq * TQ + row) * Dc + part * 16);
        #pragma unroll
        for (int s = 0; s < 4; s++) orow[s] = o[s];
    }
}

extern "C" void kernel_launch(void* const* d_in, const int* in_sizes, int n_in,
                              void* d_out, int out_size) {
    const float* q = (const float*)d_in[0];
    const float* k = (const float*)d_in[1];
    const float* v = (const float*)d_in[2];

    const size_t outElems  = (size_t)Bc * Lc * Dc;          //  1,048,576
    const size_t attnElems = (size_t)Bc * Lc * (size_t)Lc;  // 67,108,864

    float* out  = nullptr;
    float* attn = nullptr;
    size_t total = (size_t)out_size;
    if (total >= outElems + attnElems) {
        out  = (float*)d_out;
        attn = (float*)d_out + outElems;
    } else if (total >= attnElems) {
        attn = (float*)d_out;
    } else {
        out = (float*)d_out;
    }

    cudaFuncSetAttribute(sparse_attn_kernel,
                         cudaFuncAttributeMaxDynamicSharedMemorySize, SMEM_BYTES);

    dim3 grid(Lc / TQ, Bc);   // (64, 4) = 256 CTAs -> 2 per SM
    sparse_attn_kernel<<<grid, NTHREADS, SMEM_BYTES>>>(q, k, v, out, attn);
}

// round 6
// speedup vs baseline: 1.2929x; 1.1325x over previous
#include <cuda_runtime.h>
#include <cstdint>

// Problem constants (B=4, L=4096, D=64 — fixed by the dataset).
#define Bc 4
#define Lc 4096
#define Dc 64
#define TQ 64                // q rows per CTA
#define TK 256               // k rows per chunk
#define NCHUNK (Lc / TK)     // 16
#define NTHREADS 256
#define EPSf 1e-7f

// ---- packed fp32x2 FMA (Blackwell): doubles fp32 FMA throughput ----
union F2 { float2 f; unsigned long long u; };
__device__ __forceinline__ void ffma2(F2& d, const F2& a, const F2& b) {
    asm("fma.rn.f32x2 %0, %1, %2, %0;" : "+l"(d.u) : "l"(a.u), "l"(b.u));
}

// ---- 32-bit sortable key: [monotone float bits, 11-bit mantissa][12-bit col idx]
__device__ __forceinline__ unsigned key_pack(float s, int col) {
    unsigned u = __float_as_uint(s);
    u ^= (unsigned)((int)u >> 31) | 0x80000000u;   // order-preserving bit trick
    return (u & 0xFFFFF000u) | (unsigned)col;      // truncate 12 LSBs, embed col
}

__device__ __forceinline__ void ins5(unsigned* K5, unsigned kk) {
    if (kk > K5[4]) {
        if (kk > K5[2]) {
            if (kk > K5[0])      { K5[4]=K5[3];K5[3]=K5[2];K5[2]=K5[1];K5[1]=K5[0];K5[0]=kk; }
            else if (kk > K5[1]) { K5[4]=K5[3];K5[3]=K5[2];K5[2]=K5[1];K5[1]=kk; }
            else                 { K5[4]=K5[3];K5[3]=K5[2];K5[2]=kk; }
        } else {
            if (kk > K5[3]) { K5[4]=K5[3]; K5[3]=kk; } else K5[4]=kk;
        }
    }
}

// Shared memory layout (floats):
//   Qt   [    0,  4096)  : Q tile transposed [64 d][64 row], pre-scaled 1/8
//   Kt   [ 4096, 20480)  : K chunk transposed [64 d][256 col]
//        (post-loop scratch alias: keys uint[64][16][5] @ +0 (5120),
//                                  sZs  float[64][16]   @ +5120 (1024))
//   sW   [20480, 20800)  : final weights 64*5
//   sIdx [20800, 21120)  : final indices 64*5 (int)
#define SMEM_FLOATS 21120
#define SMEM_BYTES  (SMEM_FLOATS * 4)

extern "C" __global__ void __launch_bounds__(NTHREADS, 2)
sparse_attn_kernel(const float* __restrict__ q,
                   const float* __restrict__ k,
                   const float* __restrict__ v,
                   float* __restrict__ out,     // may be null
                   float* __restrict__ attn)    // may be null
{
    extern __shared__ float smem[];
    float* Qt   = smem;                 // [d*64 + row]
    float* Kt   = smem + 4096;          // [d*256 + col]
    float* sW   = smem + 20480;
    int*   sIdx = (int*)(smem + 20800);
    unsigned* sK  = (unsigned*)(smem + 4096);   // scratch alias (post-loop)
    float*    sZs = smem + 4096 + 5120;         // scratch alias (post-loop)

    const int tid = threadIdx.x;
    const int ty  = tid >> 4;      // 0..15 : q sub-block (4 rows each)
    const int tx  = tid & 15;      // 0..15 : k sub-block (4 groups of 4 cols)
    const int bq  = blockIdx.x;    // q tile (64 rows)
    const int b   = blockIdx.y;    // batch

    const float* qb = q + ((size_t)b * Lc + (size_t)bq * TQ) * Dc;
    const float* kb = k + (size_t)b * Lc * Dc;
    const float* vb = v + (size_t)b * Lc * Dc;

    // ---- Q tile -> Qt[d][row], scaled by 1/temperature ----
    #pragma unroll
    for (int it = 0; it < 4; it++) {
        int idx = it * NTHREADS + tid;      // 0..1023
        int row = idx & 63, seg = idx >> 6; // seg 0..15
        float4 t = *(const float4*)(qb + row * Dc + seg * 4);
        Qt[(seg * 4 + 0) * TQ + row] = t.x * 0.125f;
        Qt[(seg * 4 + 1) * TQ + row] = t.y * 0.125f;
        Qt[(seg * 4 + 2) * TQ + row] = t.z * 0.125f;
        Qt[(seg * 4 + 3) * TQ + row] = t.w * 0.125f;
    }

    // ---- zero-fill this CTA's attn rows (64*4096 f32, contiguous) ----
    if (attn) {
        float4 z4 = make_float4(0.f, 0.f, 0.f, 0.f);
        float4* ap = (float4*)(attn + ((size_t)b * Lc + (size_t)bq * TQ) * Lc);
        #pragma unroll 4
        for (int i = tid; i < TQ * Lc / 4; i += NTHREADS) ap[i] = z4;
    }

    float    Zl[4];
    unsigned key[4][5];                    // descending per row
    #pragma unroll
    for (int r = 0; r < 4; r++) {
        Zl[r] = 0.f;
        #pragma unroll
        for (int t = 0; t < 5; t++) key[r][t] = 0u;
    }

    for (int ch = 0; ch < NCHUNK; ch++) {
        __syncthreads();  // protect Kt from previous readers
        // ---- K chunk -> Kt[d][col] (warp = 32 cols, fixed seg: conflict-free)
        #pragma unroll
        for (int it = 0; it < 16; it++) {
            int idx = it * NTHREADS + tid;        // 0..4095
            int col = idx & 255, seg = idx >> 8;  // seg 0..15
            float4 t = *(const float4*)(kb + ((size_t)ch * TK + col) * Dc + seg * 4);
            Kt[(seg * 4 + 0) * TK + col] = t.x;
            Kt[(seg * 4 + 1) * TK + col] = t.y;
            Kt[(seg * 4 + 2) * TK + col] = t.z;
            Kt[(seg * 4 + 3) * TK + col] = t.w;
        }
        __syncthreads();

        // ---- 64x256 S tile: 4 rows x 16 cols per thread.
        //      Col groups g=0..3 : cols g*64 + tx*4 .. +3.
        //      f32x2 pairs = adjacent COLUMNS -> b pairs direct from LDS.128,
        //      only the 4 a-values need duplication. ----
        F2 acc[4][8];
        #pragma unroll
        for (int r = 0; r < 4; r++)
            #pragma unroll
            for (int cp = 0; cp < 8; cp++) acc[r][cp].f = make_float2(0.f, 0.f);

        #pragma unroll 4
        for (int kk = 0; kk < Dc; kk++) {
            float4 a  = *(const float4*)(Qt + kk * TQ + ty * 4);          // 4 rows
            float4 b0 = *(const float4*)(Kt + kk * TK +   0 + tx * 4);
            float4 b1 = *(const float4*)(Kt + kk * TK +  64 + tx * 4);
            float4 b2 = *(const float4*)(Kt + kk * TK + 128 + tx * 4);
            float4 b3 = *(const float4*)(Kt + kk * TK + 192 + tx * 4);
            F2 bp[8];
            bp[0].f = make_float2(b0.x, b0.y); bp[1].f = make_float2(b0.z, b0.w);
            bp[2].f = make_float2(b1.x, b1.y); bp[3].f = make_float2(b1.z, b1.w);
            bp[4].f = make_float2(b2.x, b2.y); bp[5].f = make_float2(b2.z, b2.w);
            bp[6].f = make_float2(b3.x, b3.y); bp[7].f = make_float2(b3.z, b3.w);
            float as[4] = {a.x, a.y, a.z, a.w};
            #pragma unroll
            for (int r = 0; r < 4; r++) {
                F2 ad; ad.f = make_float2(as[r], as[r]);
                #pragma unroll
                for (int cp = 0; cp < 8; cp++) ffma2(acc[r][cp], ad, bp[cp]);
            }
        }

        // ---- epilogue: Z partial sums + packed-key top-5 ----
        const int cbase = ch * TK + tx * 4;
        #pragma unroll
        for (int r = 0; r < 4; r++) {
            #pragma unroll
            for (int cp = 0; cp < 8; cp++) {
                int c0 = cbase + (cp >> 1) * 64 + (cp & 1) * 2;
                float s0 = acc[r][cp].f.x;
                float s1 = acc[r][cp].f.y;
                Zl[r] += __expf(s0);
                Zl[r] += __expf(s1);
                ins5(key[r], key_pack(s0, c0));
                ins5(key[r], key_pack(s1, c0 + 1));
            }
        }
    }

    __syncthreads();   // all Kt reads done; safe to alias scratch over Kt
    // ---- dump partials: 16 partials per row ----
    #pragma unroll
    for (int r = 0; r < 4; r++) {
        int row = ty * 4 + r;
        sZs[row * 16 + tx] = Zl[r];
        unsigned* dst = sK + (row * 16 + tx) * 5;
        #pragma unroll
        for (int t = 0; t < 5; t++) dst[t] = key[r][t];
    }
    __syncthreads();

    // ---- one thread per q-row: merge keys, recompute logits, sparsify ----
    if (tid < TQ) {
        const int row = tid;
        float Z = 0.f;
        unsigned m0 = 0, m1 = 0, m2 = 0, m3 = 0, m4 = 0;
        for (int x = 0; x < 16; x++) {
            Z += sZs[row * 16 + x];
            const unsigned* src = sK + (row * 16 + x) * 5;
            #pragma unroll
            for (int t = 0; t < 5; t++) {
                unsigned kk = src[t];
                if (kk <= m4) break;       // lists sorted descending
                if (kk > m2) {
                    if (kk > m0)      { m4=m3; m3=m2; m2=m1; m1=m0; m0=kk; }
                    else if (kk > m1) { m4=m3; m3=m2; m2=m1; m1=kk; }
                    else              { m4=m3; m3=m2; m2=kk; }
                } else {
                    if (kk > m3) { m4=m3; m3=kk; } else m4=kk;
                }
            }
        }
        int idx5[5] = { (int)(m0 & 0xFFFu), (int)(m1 & 0xFFFu), (int)(m2 & 0xFFFu),
                        (int)(m3 & 0xFFFu), (int)(m4 & 0xFFFu) };
        // exact logits for the 5 winners: Qt (pre-scaled) . k[idx]
        float e5[5];
        #pragma unroll
        for (int t = 0; t < 5; t++) {
            const float4* kr = (const float4*)(kb + (size_t)idx5[t] * Dc);
            float s = 0.f;
            #pragma unroll
            for (int d4 = 0; d4 < 16; d4++) {
                float4 kv = kr[d4];
                s += Qt[(d4 * 4 + 0) * TQ + row] * kv.x;
                s += Qt[(d4 * 4 + 1) * TQ + row] * kv.y;
                s += Qt[(d4 * 4 + 2) * TQ + row] * kv.z;
                s += Qt[(d4 * 4 + 3) * TQ + row] * kv.w;
            }
            e5[t] = __expf(s);
        }
        float invZ = 1.0f / Z;
        float pmin = fminf(fminf(fminf(e5[0], e5[1]), fminf(e5[2], e5[3])), e5[4]);
        float delta = pmin * invZ + EPSf;
        float w[5], wsum = 0.f;
        #pragma unroll
        for (int t = 0; t < 5; t++) { w[t] = fmaxf(e5[t] * invZ - delta, 0.f); wsum += w[t]; }
        float inv = 1.0f / (wsum + EPSf);
        #pragma unroll
        for (int t = 0; t < 5; t++) {
            w[t] *= inv;
            sW[row * 5 + t]   = w[t];
            sIdx[row * 5 + t] = idx5[t];
        }
        if (attn) {
            float* arow = attn + ((size_t)b * Lc + (size_t)bq * TQ + row) * Lc;
            #pragma unroll
            for (int t = 0; t < 5; t++) arow[idx5[t]] = w[t];
        }
    }
    __syncthreads();

    // ---- out = sparse attn @ v : 4 threads per row, 16 dims each ----
    if (out) {
        int row  = tid >> 2;       // 0..63
        int part = tid & 3;        // 16 floats = 4 float4
        float4 o[4];
        #pragma unroll
        for (int s = 0; s < 4; s++) o[s] = make_float4(0.f, 0.f, 0.f, 0.f);
        #pragma unroll
        for (int t = 0; t < 5; t++) {
            float wt = sW[row * 5 + t];
            const float4* vr =
                (const float4*)(vb + (size_t)sIdx[row * 5 + t] * Dc + part * 16);
            #pragma unroll
            for (int s = 0; s < 4; s++) {
                float4 x = vr[s];
                o[s].x += wt * x.x; o[s].y += wt * x.y;
                o[s].z += wt * x.z; o[s].w += wt * x.w;
            }
        }
        float4* orow =
            (float4*)(out + ((size_t)b * Lc + (size_t)bq * TQ + row) * Dc + part * 16);
        #pragma unroll
        for (int s = 0; s < 4; s++) orow[s] = o[s];
    }
}

extern "C" void kernel_launch(void* const* d_in, const int* in_sizes, int n_in,
                              void* d_out, int out_size) {
    const float* q = (const float*)d_in[0];
    const float* k = (const float*)d_in[1];
    const float* v = (const float*)d_in[2];

    const size_t outElems  = (size_t)Bc * Lc * Dc;          //  1,048,576
    const size_t attnElems = (size_t)Bc * Lc * (size_t)Lc;  // 67,108,864

    float* out  = nullptr;
    float* attn = nullptr;
    size_t total = (size_t)out_size;
    if (total >= outElems + attnElems) {
        out  = (float*)d_out;
        attn = (float*)d_out + outElems;
    } else if (total >= attnElems) {
        attn = (float*)d_out;
    } else {
        out = (float*)d_out;
    }

    cudaFuncSetAttribute(sparse_attn_kernel,
                         cudaFuncAttributeMaxDynamicSharedMemorySize, SMEM_BYTES);

    dim3 grid(Lc / TQ, Bc);   // (64, 4) = 256 CTAs -> 2 per SM
    sparse_attn_kernel<<<grid, NTHREADS, SMEM_BYTES>>>(q, k, v, out, attn);
}

// round 10
// speedup vs baseline: 1.5022x; 1.1619x over previous
#include <cuda_runtime.h>
#include <cuda_bf16.h>
#include <cstdint>

// Problem constants (B=4, L=4096, D=64 — fixed by the dataset).
#define Bc 4
#define Lc 4096
#define Dc 64
#define TQ 64                // q rows per CTA
#define TK 128               // k cols per chunk
#define NCHUNK (Lc / TK)     // 32
#define NTHREADS 256
#define EPSf 1e-7f

// ---- smem byte offsets ----
#define QS_OFF 0             // Q tile bf16: 64 rows x 128B (sw128)          = 8192
#define KS_OFF 8192          // K tile bf16: 128 rows x 128B (sw128)         = 16384
// post-mainloop scratch alias (Q/K tiles dead):
#define SCRK_OFF 0           // u32 [64 rows][16 partials][6]                = 24576
#define SCRZ_OFF 24576       // f32 [64][16]                                 = 4096
#define SCRW_OFF 28672       // f32 [64*5]                                   = 1280
#define SCRI_OFF 29952       // i32 [64*5]                                   = 1280
#define SMEM_BYTES 31232

__device__ __forceinline__ uint32_t smem_u32(const void* p) {
    uint32_t a;
    asm("{ .reg .u64 t; cvta.to.shared.u64 t, %1; cvt.u32.u64 %0, t; }" : "=r"(a) : "l"(p));
    return a;
}
__device__ __forceinline__ uint32_t sw128(uint32_t off) { return off ^ ((off >> 3) & 0x70); }

__device__ __forceinline__ void ldsm_x4(uint32_t* r, uint32_t addr) {
    asm volatile("ldmatrix.sync.aligned.m8n8.x4.shared.b16 {%0,%1,%2,%3}, [%4];"
                 : "=r"(r[0]), "=r"(r[1]), "=r"(r[2]), "=r"(r[3]) : "r"(addr));
}
__device__ __forceinline__ void ldsm_x2(uint32_t* r, uint32_t addr) {
    asm volatile("ldmatrix.sync.aligned.m8n8.x2.shared.b16 {%0,%1}, [%2];"
                 : "=r"(r[0]), "=r"(r[1]) : "r"(addr));
}
__device__ __forceinline__ void mma_bf16(float* c, const uint32_t* a, const uint32_t* b) {
    asm volatile(
        "mma.sync.aligned.m16n8k16.row.col.f32.bf16.bf16.f32 "
        "{%0,%1,%2,%3}, {%4,%5,%6,%7}, {%8,%9}, {%0,%1,%2,%3};"
        : "+f"(c[0]), "+f"(c[1]), "+f"(c[2]), "+f"(c[3])
        : "r"(a[0]), "r"(a[1]), "r"(a[2]), "r"(a[3]), "r"(b[0]), "r"(b[1]));
}
__device__ __forceinline__ void store_bf16x4(char* dst, float4 t) {
    __nv_bfloat162 lo = __floats2bfloat162_rn(t.x, t.y);
    __nv_bfloat162 hi = __floats2bfloat162_rn(t.z, t.w);
    uint2 u;
    u.x = *(uint32_t*)&lo;
    u.y = *(uint32_t*)&hi;
    *(uint2*)dst = u;
}

// ---- 32-bit sortable key: [monotone float bits, 20 MSBs][12-bit col idx] ----
__device__ __forceinline__ unsigned key_pack(float s, int col) {
    unsigned u = __float_as_uint(s);
    u ^= (unsigned)((int)u >> 31) | 0x80000000u;
    return (u & 0xFFFFF000u) | (unsigned)col;
}
// descending top-6 insert (sorted array, rare-taken body)
__device__ __forceinline__ void ins6(unsigned* K, unsigned kk) {
    if (kk > K[5]) {
        K[5] = kk;
        #pragma unroll
        for (int i = 5; i > 0; i--) {
            if (K[i] > K[i - 1]) { unsigned t = K[i]; K[i] = K[i - 1]; K[i - 1] = t; }
            else break;
        }
    }
}

extern "C" __global__ void __launch_bounds__(NTHREADS, 2)
sparse_attn_mma_kernel(const float* __restrict__ q,
                       const float* __restrict__ k,
                       const float* __restrict__ v,
                       float* __restrict__ out,     // may be null
                       float* __restrict__ attn)    // may be null
{
    __shared__ __align__(1024) char smem[SMEM_BYTES];
    const uint32_t sb = smem_u32(smem);

    const int tid  = threadIdx.x;
    const int wid  = tid >> 5;         // 0..7
    const int lane = tid & 31;
    const int wm   = wid & 1;          // M block (32 rows each)
    const int wn   = wid >> 1;         // N block (32 cols each)
    const int bq   = blockIdx.x;       // q tile (64 rows)
    const int b    = blockIdx.y;       // batch

    const float* qb = q + ((size_t)b * Lc + (size_t)bq * TQ) * Dc;
    const float* kb = k + (size_t)b * Lc * Dc;
    const float* vb = v + (size_t)b * Lc * Dc;

    // ---- Q tile -> bf16 smem (sw128), pre-scaled by 1/temperature ----
    #pragma unroll
    for (int it = 0; it < 4; it++) {
        int idx4 = it * NTHREADS + tid;        // 0..1023 float4s
        int row = idx4 >> 4, colf = (idx4 & 15) * 4;
        float4 t = *(const float4*)(qb + row * Dc + colf);
        t.x *= 0.125f; t.y *= 0.125f; t.z *= 0.125f; t.w *= 0.125f;
        store_bf16x4(smem + QS_OFF + sw128(row * 128 + colf * 2), t);
    }

    float4* attn_fill = attn ? (float4*)(attn + ((size_t)b * Lc + (size_t)bq * TQ) * Lc)
                             : (float4*)0;

    float    Zl[4];
    unsigned key[4][6];
    #pragma unroll
    for (int r = 0; r < 4; r++) {
        Zl[r] = 0.f;
        #pragma unroll
        for (int t = 0; t < 6; t++) key[r][t] = 0u;
    }

    // ldmatrix lane-address components
    const int a_row = wm * 32 + (lane & 15);          // + mt*16
    const int a_kof = (lane >> 4) * 16;               // + ks*32
    const int b_rowbase = wn * 32 + (lane & 7);       // + nt*8
    const int b_kof = ((lane >> 3) & 1) * 16;         // + ks*32

    for (int ch = 0; ch < NCHUNK; ch++) {
        __syncthreads();   // previous chunk's ldmatrix reads done

        // ---- K chunk -> bf16 smem [n][k] (sw128) ----
        #pragma unroll
        for (int it = 0; it < 8; it++) {
            int idx4 = it * NTHREADS + tid;    // 0..2047 float4s
            int row = idx4 >> 4, colf = (idx4 & 15) * 4;
            float4 t = *(const float4*)(kb + ((size_t)ch * TK + row) * Dc + colf);
            store_bf16x4(smem + KS_OFF + sw128(row * 128 + colf * 2), t);
        }

        // ---- spread attn zero-fill across chunks (8 float4 / thread) ----
        if (attn_fill) {
            float4 z4 = make_float4(0.f, 0.f, 0.f, 0.f);
            int base = ch * 2048;              // 65536 total / 32 chunks
            #pragma unroll
            for (int j = 0; j < 8; j++) attn_fill[base + j * NTHREADS + tid] = z4;
        }
        __syncthreads();   // K tile visible

        // ---- QK^T 64x128 via HMMA: per warp 2x4 m16n8 tiles, 4 k-steps ----
        float acc[2][4][4];
        #pragma unroll
        for (int mt = 0; mt < 2; mt++)
            #pragma unroll
            for (int nt = 0; nt < 4; nt++)
                #pragma unroll
                for (int c = 0; c < 4; c++) acc[mt][nt][c] = 0.f;

        #pragma unroll
        for (int ks = 0; ks < 4; ks++) {
            uint32_t afr[2][4], bfr[4][2];
            #pragma unroll
            for (int mt = 0; mt < 2; mt++)
                ldsm_x4(afr[mt], sb + QS_OFF +
                        sw128((uint32_t)(a_row + mt * 16) * 128 + ks * 32 + a_kof));
            #pragma unroll
            for (int nt = 0; nt < 4; nt++)
                ldsm_x2(bfr[nt], sb + KS_OFF +
                        sw128((uint32_t)(b_rowbase + nt * 8) * 128 + ks * 32 + b_kof));
            #pragma unroll
            for (int mt = 0; mt < 2; mt++)
                #pragma unroll
                for (int nt = 0; nt < 4; nt++)
                    mma_bf16(acc[mt][nt], afr[mt], bfr[nt]);
        }

        // ---- epilogue: Z partials + packed-key top-6 ----
        #pragma unroll
        for (int mt = 0; mt < 2; mt++) {
            #pragma unroll
            for (int nt = 0; nt < 4; nt++) {
                int col0 = ch * TK + wn * 32 + nt * 8 + (lane & 3) * 2;
                #pragma unroll
                for (int h = 0; h < 2; h++) {
                    float s0 = acc[mt][nt][h * 2 + 0];
                    float s1 = acc[mt][nt][h * 2 + 1];
                    int ri = mt * 2 + h;
                    Zl[ri] += __expf(s0) + __expf(s1);
                    ins6(key[ri], key_pack(s0, col0));
                    ins6(key[ri], key_pack(s1, col0 + 1));
                }
            }
        }
    }

    __syncthreads();   // mainloop smem reads done; alias scratch
    // ---- dump partials: 16 per q-row (4 lanes x 4 N-warps), 6 keys each ----
    {
        unsigned* sK = (unsigned*)(smem + SCRK_OFF);
        float*    sZ = (float*)(smem + SCRZ_OFF);
        int px = wn * 4 + (lane & 3);
        #pragma unroll
        for (int ri = 0; ri < 4; ri++) {
            int mt = ri >> 1, h = ri & 1;
            int row = wm * 32 + mt * 16 + h * 8 + (lane >> 2);
            sZ[row * 16 + px] = Zl[ri];
            unsigned* dst = sK + (row * 16 + px) * 6;
            #pragma unroll
            for (int t = 0; t < 6; t++) dst[t] = key[ri][t];
        }
    }
    __syncthreads();

    // ---- one thread per q-row: merge to top-8, exact fp32 re-rank, sparsify ----
    if (tid < TQ) {
        const int row = tid;
        const unsigned* sK = (const unsigned*)(smem + SCRK_OFF);
        const float*    sZ = (const float*)(smem + SCRZ_OFF);
        float Z = 0.f;
        unsigned m[8];
        #pragma unroll
        for (int t = 0; t < 8; t++) m[t] = 0u;
        for (int x = 0; x < 16; x++) {
            Z += sZ[row * 16 + x];
            const unsigned* src = sK + (row * 16 + x) * 6;
            #pragma unroll
            for (int t = 0; t < 6; t++) {
                unsigned kk = src[t];
                if (kk <= m[7]) break;     // partial lists sorted descending
                m[7] = kk;
                #pragma unroll
                for (int i = 7; i > 0; i--) {
                    if (m[i] > m[i - 1]) { unsigned tmp = m[i]; m[i] = m[i - 1]; m[i - 1] = tmp; }
                    else break;
                }
            }
        }
        // exact fp32 logits for all 8 candidates
        const float4* q4 = (const float4*)(qb + (size_t)row * Dc);
        float e8[8];
        int   idx8[8];
        #pragma unroll
        for (int t = 0; t < 8; t++) {
            int ci = (int)(m[t] & 0xFFFu);
            idx8[t] = ci;
            const float4* kr = (const float4*)(kb + (size_t)ci * Dc);
            float s = 0.f;
            #pragma unroll
            for (int d4 = 0; d4 < 16; d4++) {
                float4 kv = kr[d4], qv = q4[d4];
                s += qv.x * kv.x + qv.y * kv.y + qv.z * kv.z + qv.w * kv.w;
            }
            e8[t] = __expf(s * 0.125f);
        }
        // exact insertion sort of 8 (descending by value)
        #pragma unroll
        for (int i = 1; i < 8; i++) {
            float ev = e8[i]; int iv = idx8[i];
            int j = i;
            #pragma unroll
            for (int jj = 0; jj < 7; jj++) {
                if (j > 0 && e8[j - 1] < ev) { e8[j] = e8[j - 1]; idx8[j] = idx8[j - 1]; j--; }
            }
            e8[j] = ev; idx8[j] = iv;
        }
        float invZ = 1.0f / Z;
        float delta = e8[4] * invZ + EPSf;    // exact 5th-largest probability
        float w[5], wsum = 0.f;
        #pragma unroll
        for (int t = 0; t < 5; t++) { w[t] = fmaxf(e8[t] * invZ - delta, 0.f); wsum += w[t]; }
        float inv = 1.0f / (wsum + EPSf);
        float* sW  = (float*)(smem + SCRW_OFF);
        int*   sIx = (int*)(smem + SCRI_OFF);
        #pragma unroll
        for (int t = 0; t < 5; t++) {
            w[t] *= inv;
            sW[row * 5 + t]  = w[t];
            sIx[row * 5 + t] = idx8[t];
        }
        if (attn) {
            float* arow = attn + ((size_t)b * Lc + (size_t)bq * TQ + row) * Lc;
            #pragma unroll
            for (int t = 0; t < 5; t++) arow[idx8[t]] = w[t];
        }
    }
    __syncthreads();

    // ---- out = sparse attn @ v : 4 threads per row, 16 dims each ----
    if (out) {
        int row  = tid >> 2;       // 0..63
        int part = tid & 3;        // 16 floats = 4 float4
        const float* sW  = (const float*)(smem + SCRW_OFF);
        const int*   sIx = (const int*)(smem + SCRI_OFF);
        float4 o[4];
        #pragma unroll
        for (int s = 0; s < 4; s++) o[s] = make_float4(0.f, 0.f, 0.f, 0.f);
        #pragma unroll
        for (int t = 0; t < 5; t++) {
            float wt = sW[row * 5 + t];
            const float4* vr =
                (const float4*)(vb + (size_t)sIx[row * 5 + t] * Dc + part * 16);
            #pragma unroll
            for (int s = 0; s < 4; s++) {
                float4 x = vr[s];
                o[s].x += wt * x.x; o[s].y += wt * x.y;
                o[s].z += wt * x.z; o[s].w += wt * x.w;
            }
        }
        float4* orow =
            (float4*)(out + ((size_t)b * Lc + (size_t)bq * TQ + row) * Dc + part * 16);
        #pragma unroll
        for (int s = 0; s < 4; s++) orow[s] = o[s];
    }
}

extern "C" void kernel_launch(void* const* d_in, const int* in_sizes, int n_in,
                              void* d_out, int out_size) {
    const float* q = (const float*)d_in[0];
    const float* k = (const float*)d_in[1];
    const float* v = (const float*)d_in[2];

    const size_t outElems  = (size_t)Bc * Lc * Dc;          //  1,048,576
    const size_t attnElems = (size_t)Bc * Lc * (size_t)Lc;  // 67,108,864

    float* out  = nullptr;
    float* attn = nullptr;
    size_t total = (size_t)out_size;
    if (total >= outElems + attnElems) {
        out  = (float*)d_out;
        attn = (float*)d_out + outElems;
    } else if (total >= attnElems) {
        attn = (float*)d_out;
    } else {
        out = (float*)d_out;
    }

    dim3 grid(Lc / TQ, Bc);   // (64, 4) = 256 CTAs -> 2 per SM
    sparse_attn_mma_kernel<<<grid, NTHREADS>>>(q, k, v, out, attn);
}